// round 10
// baseline (speedup 1.0000x reference)
#include <cuda_runtime.h>
#include <cuda_fp16.h>
#include <cstdint>

#define SEQ 3120
#define DIM 1536
#define NH 12
#define HD 128
#define FRAME 1560
#define NQKV (3*DIM)

// ---------------- scratch (device globals; no allocation allowed) -------------
__device__ float  buf_qkv[(size_t)SEQ * NQKV];     // fp32 QKV proj output
__device__ __half hb_q[(size_t)NH * SEQ * HD];     // [h][s][d], pre-scaled
__device__ __half hb_k[(size_t)NH * SEQ * HD];     // [h][s][d]
__device__ __half hb_v[(size_t)NH * HD * SEQ];     // [h][d][s]  (TRANSPOSED)
__device__ __half hb_att[(size_t)SEQ * DIM];       // [s][h*128+d]
__device__ __half hb_x[(size_t)SEQ * DIM];         // fp16(hidden)
__device__ __half hb_wqt[(size_t)NQKV * DIM];      // fp16(w_qkv^T) [N][K]
__device__ __half hb_wot[(size_t)DIM * DIM];       // fp16(w_out^T) [N][K]

// ---------------- helpers -----------------------------------------------------
__device__ __forceinline__ uint32_t packh2(float a, float b) {
    __half2 h = __floats2half2_rn(a, b);
    return *reinterpret_cast<uint32_t*>(&h);
}

__device__ __forceinline__ void mma16(float* d, const uint32_t* a, const uint32_t* b) {
    asm volatile(
        "mma.sync.aligned.m16n8k16.row.col.f32.f16.f16.f32 "
        "{%0,%1,%2,%3},{%4,%5,%6,%7},{%8,%9},{%0,%1,%2,%3};"
        : "+f"(d[0]), "+f"(d[1]), "+f"(d[2]), "+f"(d[3])
        : "r"(a[0]), "r"(a[1]), "r"(a[2]), "r"(a[3]), "r"(b[0]), "r"(b[1]));
}

__device__ __forceinline__ void cpa16(uint32_t s, const void* g, bool v) {
    asm volatile("cp.async.ca.shared.global [%0], [%1], 16, %2;"
                 :: "r"(s), "l"(g), "r"(v ? 16 : 0));
}
__device__ __forceinline__ void cpcommit() {
    asm volatile("cp.async.commit_group;");
}
template<int N> __device__ __forceinline__ void cpwait() {
    asm volatile("cp.async.wait_group %0;" :: "n"(N));
}

// ---------------- pre-passes --------------------------------------------------
__global__ void __launch_bounds__(256) cvt_h(
    const float* __restrict__ in, __half* __restrict__ out, int n4)
{
    int i = blockIdx.x * 256 + threadIdx.x;
    if (i < n4) {
        float4 v = ((const float4*)in)[i];
        uint2 o;
        o.x = packh2(v.x, v.y);
        o.y = packh2(v.z, v.w);
        ((uint2*)out)[i] = o;
    }
}

__global__ void __launch_bounds__(256) transpose_h(
    const float* __restrict__ in, __half* __restrict__ out, int R, int C)
{
    __shared__ float tb[32][33];
    const int bx = blockIdx.x * 32;
    const int by = blockIdx.y * 32;
    const int tx = threadIdx.x & 31, ty = threadIdx.x >> 5;
#pragma unroll
    for (int i = 0; i < 4; i++)
        tb[ty + i * 8][tx] = in[(size_t)(by + ty + i * 8) * C + bx + tx];
    __syncthreads();
#pragma unroll
    for (int i = 0; i < 4; i++)
        out[(size_t)(bx + ty + i * 8) * R + by + tx] =
            __float2half_rn(tb[tx][ty + i * 8]);
}

__global__ void __launch_bounds__(256) v_transpose()
{
    __shared__ float tb[32][33];
    const int s0 = blockIdx.x * 32;
    const int d0 = blockIdx.y * 32;
    const int tx = threadIdx.x & 31, ty = threadIdx.x >> 5;
#pragma unroll
    for (int i = 0; i < 4; i++) {
        const int s = s0 + ty + i * 8;
        if (s < SEQ)
            tb[ty + i * 8][tx] = buf_qkv[(size_t)s * NQKV + 2 * DIM + d0 + tx];
    }
    __syncthreads();
    if (s0 + tx < SEQ) {
#pragma unroll
        for (int i = 0; i < 4; i++)
            hb_v[(size_t)(d0 + ty + i * 8) * SEQ + s0 + tx] =
                __float2half_rn(tb[tx][ty + i * 8]);
    }
}

// ---------------- fp16 mma.sync GEMM, 3-stage cp.async, 1 barrier/tile --------
// Order per tile: cpwait -> sync -> MMAs -> issue(kt+2) -> commit.
// The top barrier proves all warps finished iter kt-1, whose stage
// (kt-1)%3 == (kt+2)%3 is what the prefetch overwrites -> safe.
#define GKT 64
#define GTILEB (128*128)                 // 16KB per operand tile
#define GEMM_SMEM (3 * 2 * GTILEB)       // 96KB

__global__ void __launch_bounds__(256, 2) gemm_h(
    int M, int N, int K,
    const __half* __restrict__ A, const __half* __restrict__ BT,
    const float* __restrict__ bias, float* __restrict__ C)
{
    extern __shared__ char smg[];
    const uint32_t sbase = (uint32_t)__cvta_generic_to_shared(smg);
    const int tid = threadIdx.x, wid = tid >> 5, lane = tid & 31;
    const int g = lane >> 2, t = lane & 3;
    const int bm = blockIdx.y * 128, bn = blockIdx.x * 128;
    const int warpm = (wid >> 2) * 64, warpn = (wid & 3) * 32;

    const int lrow = tid >> 1;
    const int lcb = (tid & 1) * 4;
    const bool aval = (bm + lrow) < M;
    const __half* Ag = A + (size_t)(bm + lrow) * K + lcb * 8;
    const __half* Bg = BT + (size_t)(bn + lrow) * K + lcb * 8;
    uint32_t soff[4];
#pragma unroll
    for (int i = 0; i < 4; i++)
        soff[i] = (uint32_t)(lrow * 128 + (((lcb + i) * 16) ^ ((lrow & 7) * 16)));

    auto issue = [&](int st, int kt) {
        const uint32_t ab = sbase + st * 2 * GTILEB;
        const __half* ga = Ag + kt * GKT;
        const __half* gb = Bg + kt * GKT;
#pragma unroll
        for (int i = 0; i < 4; i++) {
            cpa16(ab + soff[i], ga + i * 8, aval);
            cpa16(ab + GTILEB + soff[i], gb + i * 8, true);
        }
    };

    const uint32_t* smw = (const uint32_t*)smg;

    float acc[4][4][4];
#pragma unroll
    for (int i = 0; i < 4; i++)
#pragma unroll
        for (int j = 0; j < 4; j++)
#pragma unroll
            for (int c = 0; c < 4; c++) acc[i][j][c] = 0.f;

    const int NT = K / GKT;
    issue(0, 0); cpcommit();
    issue(1, 1); cpcommit();

    for (int kt = 0; kt < NT; kt++) {
        cpwait<1>();
        __syncthreads();

        const uint32_t tw = (kt % 3) * 2 * (GTILEB / 4);
#pragma unroll
        for (int ks = 0; ks < 4; ks++) {
            uint32_t af[4][4], bf[4][2];
#pragma unroll
            for (int i = 0; i < 4; i++) {
                const int r0 = warpm + i * 16 + g, r1 = r0 + 8;
                const uint32_t x0 = (uint32_t)((ks * 8 + t) ^ ((r0 & 7) * 4));
                const uint32_t x1 = (uint32_t)((ks * 8 + t) ^ ((r1 & 7) * 4));
                const uint32_t y0 = (uint32_t)((ks * 8 + 4 + t) ^ ((r0 & 7) * 4));
                const uint32_t y1 = (uint32_t)((ks * 8 + 4 + t) ^ ((r1 & 7) * 4));
                af[i][0] = smw[tw + r0 * 32 + x0];
                af[i][1] = smw[tw + r1 * 32 + x1];
                af[i][2] = smw[tw + r0 * 32 + y0];
                af[i][3] = smw[tw + r1 * 32 + y1];
            }
#pragma unroll
            for (int j = 0; j < 4; j++) {
                const int rn = warpn + j * 8 + g;
                const uint32_t x = (uint32_t)((ks * 8 + t) ^ ((rn & 7) * 4));
                const uint32_t y = (uint32_t)((ks * 8 + 4 + t) ^ ((rn & 7) * 4));
                bf[j][0] = smw[tw + GTILEB / 4 + rn * 32 + x];
                bf[j][1] = smw[tw + GTILEB / 4 + rn * 32 + y];
            }
#pragma unroll
            for (int i = 0; i < 4; i++)
#pragma unroll
                for (int j = 0; j < 4; j++)
                    mma16(acc[i][j], af[i], bf[j]);
        }

        // prefetch AFTER the MMAs (issue-order behind HMMAs), no extra barrier
        if (kt + 2 < NT) issue((kt + 2) % 3, kt + 2);
        cpcommit();
    }

    // epilogue with bias
#pragma unroll
    for (int i = 0; i < 4; i++) {
        const int r0 = bm + warpm + i * 16 + g;
#pragma unroll
        for (int j = 0; j < 4; j++) {
            const int c0 = bn + warpn + j * 8 + 2 * t;
            const float b0 = bias[c0], b1 = bias[c0 + 1];
            if (r0 < M) {
                float2 v; v.x = acc[i][j][0] + b0; v.y = acc[i][j][1] + b1;
                *(float2*)(C + (size_t)r0 * N + c0) = v;
            }
            if (r0 + 8 < M) {
                float2 v; v.x = acc[i][j][2] + b0; v.y = acc[i][j][3] + b1;
                *(float2*)(C + (size_t)(r0 + 8) * N + c0) = v;
            }
        }
    }
}

// ---------------- RMSNorm + RoPE (Q,K); outputs fp16 --------------------------
__global__ void __launch_bounds__(256) norm_rope(
    const float* __restrict__ gamma_q, const float* __restrict__ gamma_k,
    const float* __restrict__ cosb, const float* __restrict__ sinb)
{
    const int s = blockIdx.x;
    const int tid = threadIdx.x;
    __shared__ float row[DIM];
    __shared__ float red[8];
    __shared__ float s_scale;

    const float* base = buf_qkv + (size_t)s * NQKV;
    const float qsc = 0.08838834764831845f;

    for (int sel = 0; sel < 2; sel++) {
        const float* src = base + sel * DIM;
        const float* gamma = sel ? gamma_k : gamma_q;
        __half* dst = sel ? hb_k : hb_q;
        const float post = sel ? 1.f : qsc;

        float ss = 0.f;
        for (int j = tid; j < DIM; j += 256) {
            float x = src[j];
            row[j] = x;
            ss += x * x;
        }
#pragma unroll
        for (int off = 16; off > 0; off >>= 1)
            ss += __shfl_xor_sync(0xffffffffu, ss, off);
        if ((tid & 31) == 0) red[tid >> 5] = ss;
        __syncthreads();
        if (tid == 0) {
            float tt = 0.f;
#pragma unroll
            for (int wq = 0; wq < 8; wq++) tt += red[wq];
            s_scale = rsqrtf(tt / (float)DIM + 1e-6f);
        }
        __syncthreads();
        const float scale = s_scale;

        for (int j2 = tid; j2 < DIM / 2; j2 += 256) {
            float x1 = row[2 * j2]     * scale * gamma[2 * j2];
            float x2 = row[2 * j2 + 1] * scale * gamma[2 * j2 + 1];
            const int i = j2 & 63;
            const float cc = cosb[s * 64 + i];
            const float sn = sinb[s * 64 + i];
            const int h = (2 * j2) >> 7;
            const int d = (2 * j2) & 127;
            const uint32_t p = packh2((x1 * cc - x2 * sn) * post,
                                      (x1 * sn + x2 * cc) * post);
            *(uint32_t*)(dst + ((size_t)h * SEQ + s) * HD + d) = p;
        }
        __syncthreads();
    }
}

// ---------------- fp16 flash attention with cp.async prefetch -----------------
// BQ=64, 128 threads (4 warps). Q in regs (fp16x2 pairs, pre-scaled).
// K [64 keys][136 h]; V^T [128 d][72 h]; P [64 q][72 h] packed half2.
#define ATT_BQ 64
#define KSTH 136
#define VSTH 72
#define PSTH 72
#define ATT_SMEM ((64*KSTH + 128*VSTH + 64*PSTH) * 2)

__global__ void __launch_bounds__(128) flash_h()
{
    extern __shared__ char sma[];
    __half* Kb  = (__half*)sma;                        // [64][136]
    __half* VTb = Kb + 64 * KSTH;                      // [128][72]
    uint32_t* Ps32 = (uint32_t*)(VTb + 128 * VSTH);    // [64][36] words
    const uint32_t kbase  = (uint32_t)__cvta_generic_to_shared(Kb);
    const uint32_t vtbase = (uint32_t)__cvta_generic_to_shared(VTb);
    const uint32_t* Kw = (const uint32_t*)Kb;
    const uint32_t* Vw = (const uint32_t*)VTb;

    const int h = blockIdx.y;
    const int q0 = blockIdx.x * ATT_BQ;
    const int tid = threadIdx.x, w = tid >> 5, lane = tid & 31;
    const int g = lane >> 2, t = lane & 3;

    const uint32_t* Qg = (const uint32_t*)(hb_q + (size_t)h * SEQ * HD);
    const __half* Kg = hb_k + (size_t)h * SEQ * HD;
    const __half* Vt = hb_v + (size_t)h * HD * SEQ;    // [d][s]

    const int r0 = q0 + w * 16 + g, r1 = r0 + 8;
    const int lr0 = w * 16 + g, lr1 = lr0 + 8;

    auto issueK = [&](int k0) {
        const int krow = tid >> 1;                 // 0..63
        const int cb = (tid & 1) * 8;
        const __half* src = Kg + (size_t)(k0 + krow) * HD + cb * 8;
        const uint32_t dst = kbase + (uint32_t)(krow * KSTH * 2 + cb * 16);
        const bool v = (k0 + krow) < SEQ;
#pragma unroll
        for (int c = 0; c < 8; c++)
            cpa16(dst + c * 16, src + c * 8, v);
    };
    auto issueV = [&](int k0) {
        const __half* src = Vt + (size_t)tid * SEQ + k0;   // row d = tid
        const uint32_t dst = vtbase + (uint32_t)(tid * VSTH * 2);
#pragma unroll
        for (int c = 0; c < 8; c++)
            cpa16(dst + c * 16, src + c * 8, (k0 + c * 8) < SEQ);
    };

    // Q a-frags: 8 k16-steps x 4 regs (half2-packed pairs)
    uint32_t qa[8][4];
#pragma unroll
    for (int ks = 0; ks < 8; ks++) {
        qa[ks][0] = (r0 < SEQ) ? Qg[(size_t)r0 * 64 + ks * 8 + t] : 0u;
        qa[ks][1] = (r1 < SEQ) ? Qg[(size_t)r1 * 64 + ks * 8 + t] : 0u;
        qa[ks][2] = (r0 < SEQ) ? Qg[(size_t)r0 * 64 + ks * 8 + 4 + t] : 0u;
        qa[ks][3] = (r1 < SEQ) ? Qg[(size_t)r1 * 64 + ks * 8 + 4 + t] : 0u;
    }

    float O[16][4];
#pragma unroll
    for (int j = 0; j < 16; j++)
#pragma unroll
        for (int c = 0; c < 4; c++) O[j][c] = 0.f;
    float m0 = -1e30f, m1 = -1e30f, l0 = 0.f, l1 = 0.f;

    int rl0 = (r0 / FRAME + 1) * FRAME; if (rl0 > SEQ) rl0 = SEQ;
    int rl1 = (r1 / FRAME + 1) * FRAME; if (rl1 > SEQ) rl1 = SEQ;
    int qlast = q0 + ATT_BQ - 1; if (qlast > SEQ - 1) qlast = SEQ - 1;
    int kmax = (qlast / FRAME + 1) * FRAME; if (kmax > SEQ) kmax = SEQ;

    issueK(0); cpcommit();
    issueV(0); cpcommit();

    for (int k0 = 0; k0 < kmax; k0 += 64) {
        cpwait<1>();          // K ready
        __syncthreads();

        // S = Q K^T : per warp 16 q-rows x 64 keys (8 n-tiles), 8 k16-steps
        float sf[8][4];
#pragma unroll
        for (int j = 0; j < 8; j++)
#pragma unroll
            for (int c = 0; c < 4; c++) sf[j][c] = 0.f;

#pragma unroll
        for (int ks = 0; ks < 8; ks++) {
#pragma unroll
            for (int j = 0; j < 8; j++) {
                const int rn = j * 8 + g;
                uint32_t bf[2];
                bf[0] = Kw[rn * 68 + ks * 8 + t];
                bf[1] = Kw[rn * 68 + ks * 8 + 4 + t];
                mma16(sf[j], qa[ks], bf);
            }
        }

        // mask + online softmax
        float mt0 = -1e30f, mt1 = -1e30f;
#pragma unroll
        for (int j = 0; j < 8; j++) {
            const int c = k0 + j * 8 + 2 * t;
            sf[j][0] = (c     < rl0) ? sf[j][0] : -1e30f;
            sf[j][1] = (c + 1 < rl0) ? sf[j][1] : -1e30f;
            sf[j][2] = (c     < rl1) ? sf[j][2] : -1e30f;
            sf[j][3] = (c + 1 < rl1) ? sf[j][3] : -1e30f;
            mt0 = fmaxf(mt0, fmaxf(sf[j][0], sf[j][1]));
            mt1 = fmaxf(mt1, fmaxf(sf[j][2], sf[j][3]));
        }
        mt0 = fmaxf(mt0, __shfl_xor_sync(0xffffffffu, mt0, 1));
        mt0 = fmaxf(mt0, __shfl_xor_sync(0xffffffffu, mt0, 2));
        mt1 = fmaxf(mt1, __shfl_xor_sync(0xffffffffu, mt1, 1));
        mt1 = fmaxf(mt1, __shfl_xor_sync(0xffffffffu, mt1, 2));

        const float mn0 = fmaxf(m0, mt0), mn1 = fmaxf(m1, mt1);
        const float a0 = __expf(m0 - mn0), a1 = __expf(m1 - mn1);
        float s0 = 0.f, sm1 = 0.f;
#pragma unroll
        for (int j = 0; j < 8; j++) {
            float p0 = __expf(sf[j][0] - mn0);
            float p1 = __expf(sf[j][1] - mn0);
            float p2 = __expf(sf[j][2] - mn1);
            float p3 = __expf(sf[j][3] - mn1);
            s0 += p0 + p1; sm1 += p2 + p3;
            Ps32[lr0 * 36 + j * 4 + t] = packh2(p0, p1);
            Ps32[lr1 * 36 + j * 4 + t] = packh2(p2, p3);
        }
        s0  += __shfl_xor_sync(0xffffffffu, s0, 1);
        s0  += __shfl_xor_sync(0xffffffffu, s0, 2);
        sm1 += __shfl_xor_sync(0xffffffffu, sm1, 1);
        sm1 += __shfl_xor_sync(0xffffffffu, sm1, 2);
        l0 = l0 * a0 + s0;  m0 = mn0;
        l1 = l1 * a1 + sm1; m1 = mn1;
#pragma unroll
        for (int j = 0; j < 16; j++) {
            O[j][0] *= a0; O[j][1] *= a0;
            O[j][2] *= a1; O[j][3] *= a1;
        }

        cpwait<0>();          // V ready
        __syncthreads();      // also publishes Ps

        if (k0 + 64 < kmax) issueK(k0 + 64);
        cpcommit();

        // O += P @ V : 4 k16-steps over 64 keys, 16 dv n-tiles
#pragma unroll
        for (int ks = 0; ks < 4; ks++) {
            uint32_t af[4];
            af[0] = Ps32[lr0 * 36 + ks * 8 + t];
            af[1] = Ps32[lr1 * 36 + ks * 8 + t];
            af[2] = Ps32[lr0 * 36 + ks * 8 + 4 + t];
            af[3] = Ps32[lr1 * 36 + ks * 8 + 4 + t];
#pragma unroll
            for (int j = 0; j < 16; j++) {
                const int rn = j * 8 + g;
                uint32_t bf[2];
                bf[0] = Vw[rn * 36 + ks * 8 + t];
                bf[1] = Vw[rn * 36 + ks * 8 + 4 + t];
                mma16(O[j], af, bf);
            }
        }
        __syncthreads();      // done with VTb / Ps

        if (k0 + 64 < kmax) issueV(k0 + 64);
        cpcommit();
    }

    // epilogue -> fp16 buf_att (half2 stores)
    const float inv0 = 1.f / l0, inv1 = 1.f / l1;
#pragma unroll
    for (int j = 0; j < 16; j++) {
        const int c = h * HD + j * 8 + 2 * t;
        if (r0 < SEQ)
            *(uint32_t*)(hb_att + (size_t)r0 * DIM + c) =
                packh2(O[j][0] * inv0, O[j][1] * inv0);
        if (r1 < SEQ)
            *(uint32_t*)(hb_att + (size_t)r1 * DIM + c) =
                packh2(O[j][2] * inv1, O[j][3] * inv1);
    }
}

// ---------------- launch ------------------------------------------------------
extern "C" void kernel_launch(void* const* d_in, const int* in_sizes, int n_in,
                              void* d_out, int out_size)
{
    const float* hidden  = (const float*)d_in[0];
    const float* cosb    = (const float*)d_in[1];
    const float* sinb    = (const float*)d_in[2];
    const float* w_qkv   = (const float*)d_in[3];
    const float* b_qkv   = (const float*)d_in[4];
    const float* gamma_q = (const float*)d_in[5];
    const float* gamma_k = (const float*)d_in[6];
    const float* w_out   = (const float*)d_in[7];
    const float* b_out   = (const float*)d_in[8];
    float* out = (float*)d_out;

    float* qkv_p;
    __half *x_p, *wqt_p, *wot_p, *att_p;
    cudaGetSymbolAddress((void**)&qkv_p, buf_qkv);
    cudaGetSymbolAddress((void**)&x_p,   hb_x);
    cudaGetSymbolAddress((void**)&wqt_p, hb_wqt);
    cudaGetSymbolAddress((void**)&wot_p, hb_wot);
    cudaGetSymbolAddress((void**)&att_p, hb_att);

    cudaFuncSetAttribute(gemm_h, cudaFuncAttributeMaxDynamicSharedMemorySize,
                         GEMM_SMEM);
    cudaFuncSetAttribute(flash_h, cudaFuncAttributeMaxDynamicSharedMemorySize,
                         ATT_SMEM);

    // 0) pre-passes: fp16 conversion + weight transposes
    int n4 = SEQ * DIM / 4;
    cvt_h<<<(n4 + 255) / 256, 256>>>(hidden, x_p, n4);
    {
        dim3 gt(NQKV / 32, DIM / 32);
        transpose_h<<<gt, 256>>>(w_qkv, wqt_p, DIM, NQKV);
        dim3 go(DIM / 32, DIM / 32);
        transpose_h<<<go, 256>>>(w_out, wot_p, DIM, DIM);
    }

    // 1) QKV projection (fp16 tensor cores, fp32 out)
    dim3 g1(NQKV / 128, (SEQ + 127) / 128);
    gemm_h<<<g1, 256, GEMM_SMEM>>>(SEQ, NQKV, DIM, x_p, wqt_p, b_qkv, qkv_p);

    // 2) RMSNorm + RoPE (Q,K fp16) and V transpose (fp16)
    norm_rope<<<SEQ, 256>>>(gamma_q, gamma_k, cosb, sinb);
    {
        dim3 gv((SEQ + 31) / 32, DIM / 32);
        v_transpose<<<gv, 256>>>();
    }

    // 3) attention
    dim3 g3((SEQ + ATT_BQ - 1) / ATT_BQ, NH);
    flash_h<<<g3, 128, ATT_SMEM>>>();

    // 4) output projection
    dim3 g4(DIM / 128, (SEQ + 127) / 128);
    gemm_h<<<g4, 256, GEMM_SMEM>>>(SEQ, DIM, DIM, att_p, wot_p, b_out, out);
}

// round 12
// speedup vs baseline: 1.4355x; 1.4355x over previous
#include <cuda_runtime.h>
#include <cuda_fp16.h>
#include <cstdint>

#define SEQ 3120
#define DIM 1536
#define NH 12
#define HD 128
#define FRAME 1560
#define NQKV (3*DIM)

// ---------------- scratch (device globals; no allocation allowed) -------------
__device__ float  buf_qkv[(size_t)SEQ * NQKV];     // fp32 QKV proj output
__device__ __half hb_q[(size_t)NH * SEQ * HD];     // [h][s][d], pre-scaled
__device__ __half hb_k[(size_t)NH * SEQ * HD];     // [h][s][d]
__device__ __half hb_v[(size_t)NH * HD * SEQ];     // [h][d][s]  (TRANSPOSED)
__device__ __half hb_att[(size_t)SEQ * DIM];       // [s][h*128+d]
__device__ __half hb_x[(size_t)SEQ * DIM];         // fp16(hidden)
__device__ __half hb_wqt[(size_t)NQKV * DIM];      // fp16(w_qkv^T) [N][K]
__device__ __half hb_wot[(size_t)DIM * DIM];       // fp16(w_out^T) [N][K]

// ---------------- helpers -----------------------------------------------------
__device__ __forceinline__ uint32_t packh2(float a, float b) {
    __half2 h = __floats2half2_rn(a, b);
    return *reinterpret_cast<uint32_t*>(&h);
}

__device__ __forceinline__ void mma16(float* d, const uint32_t* a, const uint32_t* b) {
    asm volatile(
        "mma.sync.aligned.m16n8k16.row.col.f32.f16.f16.f32 "
        "{%0,%1,%2,%3},{%4,%5,%6,%7},{%8,%9},{%0,%1,%2,%3};"
        : "+f"(d[0]), "+f"(d[1]), "+f"(d[2]), "+f"(d[3])
        : "r"(a[0]), "r"(a[1]), "r"(a[2]), "r"(a[3]), "r"(b[0]), "r"(b[1]));
}

__device__ __forceinline__ void cpa16(uint32_t s, const void* g, bool v) {
    asm volatile("cp.async.ca.shared.global [%0], [%1], 16, %2;"
                 :: "r"(s), "l"(g), "r"(v ? 16 : 0));
}
__device__ __forceinline__ void cpcommit() {
    asm volatile("cp.async.commit_group;");
}
template<int N> __device__ __forceinline__ void cpwait() {
    asm volatile("cp.async.wait_group %0;" :: "n"(N));
}

// ---------------- pre-passes --------------------------------------------------
__global__ void __launch_bounds__(256) cvt_h(
    const float* __restrict__ in, __half* __restrict__ out, int n4)
{
    int i = blockIdx.x * 256 + threadIdx.x;
    if (i < n4) {
        float4 v = ((const float4*)in)[i];
        uint2 o;
        o.x = packh2(v.x, v.y);
        o.y = packh2(v.z, v.w);
        ((uint2*)out)[i] = o;
    }
}

__global__ void __launch_bounds__(256) transpose_h(
    const float* __restrict__ in, __half* __restrict__ out, int R, int C)
{
    __shared__ float tb[32][33];
    const int bx = blockIdx.x * 32;
    const int by = blockIdx.y * 32;
    const int tx = threadIdx.x & 31, ty = threadIdx.x >> 5;
#pragma unroll
    for (int i = 0; i < 4; i++)
        tb[ty + i * 8][tx] = in[(size_t)(by + ty + i * 8) * C + bx + tx];
    __syncthreads();
#pragma unroll
    for (int i = 0; i < 4; i++)
        out[(size_t)(bx + ty + i * 8) * R + by + tx] =
            __float2half_rn(tb[tx][ty + i * 8]);
}

__global__ void __launch_bounds__(256) v_transpose()
{
    __shared__ float tb[32][33];
    const int s0 = blockIdx.x * 32;
    const int d0 = blockIdx.y * 32;
    const int tx = threadIdx.x & 31, ty = threadIdx.x >> 5;
#pragma unroll
    for (int i = 0; i < 4; i++) {
        const int s = s0 + ty + i * 8;
        if (s < SEQ)
            tb[ty + i * 8][tx] = buf_qkv[(size_t)s * NQKV + 2 * DIM + d0 + tx];
    }
    __syncthreads();
    if (s0 + tx < SEQ) {
#pragma unroll
        for (int i = 0; i < 4; i++)
            hb_v[(size_t)(d0 + ty + i * 8) * SEQ + s0 + tx] =
                __float2half_rn(tb[tx][ty + i * 8]);
    }
}

// ---------------- fp16 mma.sync GEMM, 3-stage cp.async (R8 structure) ---------
#define GKT 64
#define GTILEB (128*128)                 // 16KB per operand tile
#define GEMM_SMEM (3 * 2 * GTILEB)       // 96KB

__global__ void __launch_bounds__(256, 2) gemm_h(
    int M, int N, int K,
    const __half* __restrict__ A, const __half* __restrict__ BT,
    const float* __restrict__ bias, float* __restrict__ C)
{
    extern __shared__ char smg[];
    const uint32_t sbase = (uint32_t)__cvta_generic_to_shared(smg);
    const int tid = threadIdx.x, wid = tid >> 5, lane = tid & 31;
    const int g = lane >> 2, t = lane & 3;
    const int bm = blockIdx.y * 128, bn = blockIdx.x * 128;
    const int warpm = (wid >> 2) * 64, warpn = (wid & 3) * 32;

    const int lrow = tid >> 1;
    const int lcb = (tid & 1) * 4;
    const bool aval = (bm + lrow) < M;
    const __half* Ag = A + (size_t)(bm + lrow) * K + lcb * 8;
    const __half* Bg = BT + (size_t)(bn + lrow) * K + lcb * 8;
    uint32_t soff[4];
#pragma unroll
    for (int i = 0; i < 4; i++)
        soff[i] = (uint32_t)(lrow * 128 + (((lcb + i) * 16) ^ ((lrow & 7) * 16)));

    auto issue = [&](int st, int kt) {
        const uint32_t ab = sbase + st * 2 * GTILEB;
        const __half* ga = Ag + kt * GKT;
        const __half* gb = Bg + kt * GKT;
#pragma unroll
        for (int i = 0; i < 4; i++) {
            cpa16(ab + soff[i], ga + i * 8, aval);
            cpa16(ab + GTILEB + soff[i], gb + i * 8, true);
        }
    };

    const uint32_t* smw = (const uint32_t*)smg;

    float acc[4][4][4];
#pragma unroll
    for (int i = 0; i < 4; i++)
#pragma unroll
        for (int j = 0; j < 4; j++)
#pragma unroll
            for (int c = 0; c < 4; c++) acc[i][j][c] = 0.f;

    const int NT = K / GKT;
    issue(0, 0); cpcommit();
    issue(1, 1); cpcommit();

    for (int kt = 0; kt < NT; kt++) {
        cpwait<1>();
        __syncthreads();

        const uint32_t tw = (kt % 3) * 2 * (GTILEB / 4);
#pragma unroll
        for (int ks = 0; ks < 4; ks++) {
            uint32_t af[4][4], bf[4][2];
#pragma unroll
            for (int i = 0; i < 4; i++) {
                const int r0 = warpm + i * 16 + g, r1 = r0 + 8;
                const uint32_t x0 = (uint32_t)((ks * 8 + t) ^ ((r0 & 7) * 4));
                const uint32_t x1 = (uint32_t)((ks * 8 + t) ^ ((r1 & 7) * 4));
                const uint32_t y0 = (uint32_t)((ks * 8 + 4 + t) ^ ((r0 & 7) * 4));
                const uint32_t y1 = (uint32_t)((ks * 8 + 4 + t) ^ ((r1 & 7) * 4));
                af[i][0] = smw[tw + r0 * 32 + x0];
                af[i][1] = smw[tw + r1 * 32 + x1];
                af[i][2] = smw[tw + r0 * 32 + y0];
                af[i][3] = smw[tw + r1 * 32 + y1];
            }
#pragma unroll
            for (int j = 0; j < 4; j++) {
                const int rn = warpn + j * 8 + g;
                const uint32_t x = (uint32_t)((ks * 8 + t) ^ ((rn & 7) * 4));
                const uint32_t y = (uint32_t)((ks * 8 + 4 + t) ^ ((rn & 7) * 4));
                bf[j][0] = smw[tw + GTILEB / 4 + rn * 32 + x];
                bf[j][1] = smw[tw + GTILEB / 4 + rn * 32 + y];
            }
#pragma unroll
            for (int i = 0; i < 4; i++)
#pragma unroll
                for (int j = 0; j < 4; j++)
                    mma16(acc[i][j], af[i], bf[j]);
        }
        __syncthreads();
        if (kt + 2 < NT) issue((kt + 2) % 3, kt + 2);
        cpcommit();
    }

    // epilogue with bias
#pragma unroll
    for (int i = 0; i < 4; i++) {
        const int r0 = bm + warpm + i * 16 + g;
#pragma unroll
        for (int j = 0; j < 4; j++) {
            const int c0 = bn + warpn + j * 8 + 2 * t;
            const float b0 = bias[c0], b1 = bias[c0 + 1];
            if (r0 < M) {
                float2 v; v.x = acc[i][j][0] + b0; v.y = acc[i][j][1] + b1;
                *(float2*)(C + (size_t)r0 * N + c0) = v;
            }
            if (r0 + 8 < M) {
                float2 v; v.x = acc[i][j][2] + b0; v.y = acc[i][j][3] + b1;
                *(float2*)(C + (size_t)(r0 + 8) * N + c0) = v;
            }
        }
    }
}

// ---------------- RMSNorm + RoPE (Q,K); outputs fp16 --------------------------
__global__ void __launch_bounds__(256) norm_rope(
    const float* __restrict__ gamma_q, const float* __restrict__ gamma_k,
    const float* __restrict__ cosb, const float* __restrict__ sinb)
{
    const int s = blockIdx.x;
    const int tid = threadIdx.x;
    __shared__ float row[DIM];
    __shared__ float red[8];
    __shared__ float s_scale;

    const float* base = buf_qkv + (size_t)s * NQKV;
    const float qsc = 0.08838834764831845f;

    for (int sel = 0; sel < 2; sel++) {
        const float* src = base + sel * DIM;
        const float* gamma = sel ? gamma_k : gamma_q;
        __half* dst = sel ? hb_k : hb_q;
        const float post = sel ? 1.f : qsc;

        float ss = 0.f;
        for (int j = tid; j < DIM; j += 256) {
            float x = src[j];
            row[j] = x;
            ss += x * x;
        }
#pragma unroll
        for (int off = 16; off > 0; off >>= 1)
            ss += __shfl_xor_sync(0xffffffffu, ss, off);
        if ((tid & 31) == 0) red[tid >> 5] = ss;
        __syncthreads();
        if (tid == 0) {
            float tt = 0.f;
#pragma unroll
            for (int wq = 0; wq < 8; wq++) tt += red[wq];
            s_scale = rsqrtf(tt / (float)DIM + 1e-6f);
        }
        __syncthreads();
        const float scale = s_scale;

        for (int j2 = tid; j2 < DIM / 2; j2 += 256) {
            float x1 = row[2 * j2]     * scale * gamma[2 * j2];
            float x2 = row[2 * j2 + 1] * scale * gamma[2 * j2 + 1];
            const int i = j2 & 63;
            const float cc = cosb[s * 64 + i];
            const float sn = sinb[s * 64 + i];
            const int h = (2 * j2) >> 7;
            const int d = (2 * j2) & 127;
            const uint32_t p = packh2((x1 * cc - x2 * sn) * post,
                                      (x1 * sn + x2 * cc) * post);
            *(uint32_t*)(dst + ((size_t)h * SEQ + s) * HD + d) = p;
        }
        __syncthreads();
    }
}

// ---------------- fp16 flash attention (R8 structure + mask-skip) -------------
#define ATT_BQ 64
#define KSTH 136
#define VSTH 72
#define PSTH 72
#define ATT_SMEM ((64*KSTH + 128*VSTH + 64*PSTH) * 2)

__global__ void __launch_bounds__(128) flash_h()
{
    extern __shared__ char sma[];
    __half* Kb  = (__half*)sma;                        // [64][136]
    __half* VTb = Kb + 64 * KSTH;                      // [128][72]
    uint32_t* Ps32 = (uint32_t*)(VTb + 128 * VSTH);    // [64][36] words
    const uint32_t kbase  = (uint32_t)__cvta_generic_to_shared(Kb);
    const uint32_t vtbase = (uint32_t)__cvta_generic_to_shared(VTb);
    const uint32_t* Kw = (const uint32_t*)Kb;
    const uint32_t* Vw = (const uint32_t*)VTb;

    const int h = blockIdx.y;
    const int q0 = blockIdx.x * ATT_BQ;
    const int tid = threadIdx.x, w = tid >> 5, lane = tid & 31;
    const int g = lane >> 2, t = lane & 3;

    const uint32_t* Qg = (const uint32_t*)(hb_q + (size_t)h * SEQ * HD);
    const __half* Kg = hb_k + (size_t)h * SEQ * HD;
    const __half* Vt = hb_v + (size_t)h * HD * SEQ;    // [d][s]

    const int r0 = q0 + w * 16 + g, r1 = r0 + 8;
    const int lr0 = w * 16 + g, lr1 = lr0 + 8;

    auto issueK = [&](int k0) {
        const int krow = tid >> 1;                 // 0..63
        const int cb = (tid & 1) * 8;
        const __half* src = Kg + (size_t)(k0 + krow) * HD + cb * 8;
        const uint32_t dst = kbase + (uint32_t)(krow * KSTH * 2 + cb * 16);
        const bool v = (k0 + krow) < SEQ;
#pragma unroll
        for (int c = 0; c < 8; c++)
            cpa16(dst + c * 16, src + c * 8, v);
    };
    auto issueV = [&](int k0) {
        const __half* src = Vt + (size_t)tid * SEQ + k0;   // row d = tid
        const uint32_t dst = vtbase + (uint32_t)(tid * VSTH * 2);
#pragma unroll
        for (int c = 0; c < 8; c++)
            cpa16(dst + c * 16, src + c * 8, (k0 + c * 8) < SEQ);
    };

    // Q a-frags: 8 k16-steps x 4 regs (half2-packed pairs)
    uint32_t qa[8][4];
#pragma unroll
    for (int ks = 0; ks < 8; ks++) {
        qa[ks][0] = (r0 < SEQ) ? Qg[(size_t)r0 * 64 + ks * 8 + t] : 0u;
        qa[ks][1] = (r1 < SEQ) ? Qg[(size_t)r1 * 64 + ks * 8 + t] : 0u;
        qa[ks][2] = (r0 < SEQ) ? Qg[(size_t)r0 * 64 + ks * 8 + 4 + t] : 0u;
        qa[ks][3] = (r1 < SEQ) ? Qg[(size_t)r1 * 64 + ks * 8 + 4 + t] : 0u;
    }

    float O[16][4];
#pragma unroll
    for (int j = 0; j < 16; j++)
#pragma unroll
        for (int c = 0; c < 4; c++) O[j][c] = 0.f;
    float m0 = -1e30f, m1 = -1e30f, l0 = 0.f, l1 = 0.f;

    int rl0 = (r0 / FRAME + 1) * FRAME; if (rl0 > SEQ) rl0 = SEQ;
    int rl1 = (r1 / FRAME + 1) * FRAME; if (rl1 > SEQ) rl1 = SEQ;
    // lowest frame boundary within this CTA's rows: rows span q0..q0+63
    int rlmin = (q0 / FRAME + 1) * FRAME; if (rlmin > SEQ) rlmin = SEQ;
    int qlast = q0 + ATT_BQ - 1; if (qlast > SEQ - 1) qlast = SEQ - 1;
    int kmax = (qlast / FRAME + 1) * FRAME; if (kmax > SEQ) kmax = SEQ;

    issueK(0); cpcommit();
    issueV(0); cpcommit();

    for (int k0 = 0; k0 < kmax; k0 += 64) {
        cpwait<1>();          // K ready
        __syncthreads();

        // S = Q K^T : per warp 16 q-rows x 64 keys (8 n-tiles), 8 k16-steps
        float sf[8][4];
#pragma unroll
        for (int j = 0; j < 8; j++)
#pragma unroll
            for (int c = 0; c < 4; c++) sf[j][c] = 0.f;

#pragma unroll
        for (int ks = 0; ks < 8; ks++) {
#pragma unroll
            for (int j = 0; j < 8; j++) {
                const int rn = j * 8 + g;
                uint32_t bf[2];
                bf[0] = Kw[rn * 68 + ks * 8 + t];
                bf[1] = Kw[rn * 68 + ks * 8 + 4 + t];
                mma16(sf[j], qa[ks], bf);
            }
        }

        // mask only if this k-tile straddles a frame boundary for some row
        if (k0 + 64 > rlmin) {
#pragma unroll
            for (int j = 0; j < 8; j++) {
                const int c = k0 + j * 8 + 2 * t;
                sf[j][0] = (c     < rl0) ? sf[j][0] : -1e30f;
                sf[j][1] = (c + 1 < rl0) ? sf[j][1] : -1e30f;
                sf[j][2] = (c     < rl1) ? sf[j][2] : -1e30f;
                sf[j][3] = (c + 1 < rl1) ? sf[j][3] : -1e30f;
            }
        }

        // online softmax
        float mt0 = -1e30f, mt1 = -1e30f;
#pragma unroll
        for (int j = 0; j < 8; j++) {
            mt0 = fmaxf(mt0, fmaxf(sf[j][0], sf[j][1]));
            mt1 = fmaxf(mt1, fmaxf(sf[j][2], sf[j][3]));
        }
        mt0 = fmaxf(mt0, __shfl_xor_sync(0xffffffffu, mt0, 1));
        mt0 = fmaxf(mt0, __shfl_xor_sync(0xffffffffu, mt0, 2));
        mt1 = fmaxf(mt1, __shfl_xor_sync(0xffffffffu, mt1, 1));
        mt1 = fmaxf(mt1, __shfl_xor_sync(0xffffffffu, mt1, 2));

        const float mn0 = fmaxf(m0, mt0), mn1 = fmaxf(m1, mt1);
        const float a0 = __expf(m0 - mn0), a1 = __expf(m1 - mn1);
        float s0 = 0.f, sm1 = 0.f;
#pragma unroll
        for (int j = 0; j < 8; j++) {
            float p0 = __expf(sf[j][0] - mn0);
            float p1 = __expf(sf[j][1] - mn0);
            float p2 = __expf(sf[j][2] - mn1);
            float p3 = __expf(sf[j][3] - mn1);
            s0 += p0 + p1; sm1 += p2 + p3;
            Ps32[lr0 * 36 + j * 4 + t] = packh2(p0, p1);
            Ps32[lr1 * 36 + j * 4 + t] = packh2(p2, p3);
        }
        s0  += __shfl_xor_sync(0xffffffffu, s0, 1);
        s0  += __shfl_xor_sync(0xffffffffu, s0, 2);
        sm1 += __shfl_xor_sync(0xffffffffu, sm1, 1);
        sm1 += __shfl_xor_sync(0xffffffffu, sm1, 2);
        l0 = l0 * a0 + s0;  m0 = mn0;
        l1 = l1 * a1 + sm1; m1 = mn1;
#pragma unroll
        for (int j = 0; j < 16; j++) {
            O[j][0] *= a0; O[j][1] *= a0;
            O[j][2] *= a1; O[j][3] *= a1;
        }

        cpwait<0>();          // V ready
        __syncthreads();      // also publishes Ps

        if (k0 + 64 < kmax) issueK(k0 + 64);
        cpcommit();

        // O += P @ V : 4 k16-steps over 64 keys, 16 dv n-tiles
#pragma unroll
        for (int ks = 0; ks < 4; ks++) {
            uint32_t af[4];
            af[0] = Ps32[lr0 * 36 + ks * 8 + t];
            af[1] = Ps32[lr1 * 36 + ks * 8 + t];
            af[2] = Ps32[lr0 * 36 + ks * 8 + 4 + t];
            af[3] = Ps32[lr1 * 36 + ks * 8 + 4 + t];
#pragma unroll
            for (int j = 0; j < 16; j++) {
                const int rn = j * 8 + g;
                uint32_t bf[2];
                bf[0] = Vw[rn * 36 + ks * 8 + t];
                bf[1] = Vw[rn * 36 + ks * 8 + 4 + t];
                mma16(O[j], af, bf);
            }
        }
        __syncthreads();      // done with VTb / Ps

        if (k0 + 64 < kmax) issueV(k0 + 64);
        cpcommit();
    }

    // epilogue -> fp16 buf_att (half2 stores)
    const float inv0 = 1.f / l0, inv1 = 1.f / l1;
#pragma unroll
    for (int j = 0; j < 16; j++) {
        const int c = h * HD + j * 8 + 2 * t;
        if (r0 < SEQ)
            *(uint32_t*)(hb_att + (size_t)r0 * DIM + c) =
                packh2(O[j][0] * inv0, O[j][1] * inv0);
        if (r1 < SEQ)
            *(uint32_t*)(hb_att + (size_t)r1 * DIM + c) =
                packh2(O[j][2] * inv1, O[j][3] * inv1);
    }
}

// ---------------- launch ------------------------------------------------------
extern "C" void kernel_launch(void* const* d_in, const int* in_sizes, int n_in,
                              void* d_out, int out_size)
{
    const float* hidden  = (const float*)d_in[0];
    const float* cosb    = (const float*)d_in[1];
    const float* sinb    = (const float*)d_in[2];
    const float* w_qkv   = (const float*)d_in[3];
    const float* b_qkv   = (const float*)d_in[4];
    const float* gamma_q = (const float*)d_in[5];
    const float* gamma_k = (const float*)d_in[6];
    const float* w_out   = (const float*)d_in[7];
    const float* b_out   = (const float*)d_in[8];
    float* out = (float*)d_out;

    float* qkv_p;
    __half *x_p, *wqt_p, *wot_p, *att_p;
    cudaGetSymbolAddress((void**)&qkv_p, buf_qkv);
    cudaGetSymbolAddress((void**)&x_p,   hb_x);
    cudaGetSymbolAddress((void**)&wqt_p, hb_wqt);
    cudaGetSymbolAddress((void**)&wot_p, hb_wot);
    cudaGetSymbolAddress((void**)&att_p, hb_att);

    cudaFuncSetAttribute(gemm_h, cudaFuncAttributeMaxDynamicSharedMemorySize,
                         GEMM_SMEM);
    cudaFuncSetAttribute(flash_h, cudaFuncAttributeMaxDynamicSharedMemorySize,
                         ATT_SMEM);

    // 0) pre-passes: fp16 conversion + weight transposes
    int n4 = SEQ * DIM / 4;
    cvt_h<<<(n4 + 255) / 256, 256>>>(hidden, x_p, n4);
    {
        dim3 gt(NQKV / 32, DIM / 32);
        transpose_h<<<gt, 256>>>(w_qkv, wqt_p, DIM, NQKV);
        dim3 go(DIM / 32, DIM / 32);
        transpose_h<<<go, 256>>>(w_out, wot_p, DIM, DIM);
    }

    // 1) QKV projection (fp16 tensor cores, fp32 out)
    dim3 g1(NQKV / 128, (SEQ + 127) / 128);
    gemm_h<<<g1, 256, GEMM_SMEM>>>(SEQ, NQKV, DIM, x_p, wqt_p, b_qkv, qkv_p);

    // 2) RMSNorm + RoPE (Q,K fp16) and V transpose (fp16)
    norm_rope<<<SEQ, 256>>>(gamma_q, gamma_k, cosb, sinb);
    {
        dim3 gv((SEQ + 31) / 32, DIM / 32);
        v_transpose<<<gv, 256>>>();
    }

    // 3) attention
    dim3 g3((SEQ + ATT_BQ - 1) / ATT_BQ, NH);
    flash_h<<<g3, 128, ATT_SMEM>>>();

    // 4) output projection
    dim3 g4(DIM / 128, (SEQ + 127) / 128);
    gemm_h<<<g4, 256, GEMM_SMEM>>>(SEQ, DIM, DIM, att_p, wot_p, b_out, out);
}

// round 13
// speedup vs baseline: 1.5798x; 1.1005x over previous
#include <cuda_runtime.h>
#include <cuda_fp16.h>
#include <cstdint>

#define SEQ 3120
#define DIM 1536
#define NH 12
#define HD 128
#define FRAME 1560
#define NQKV (3*DIM)

// ---------------- scratch (device globals; no allocation allowed) -------------
__device__ float  buf_qkv[(size_t)SEQ * NQKV];     // fp32 QKV proj output
__device__ __half hb_q[(size_t)NH * SEQ * HD];     // [h][s][d], pre-scaled
__device__ __half hb_k[(size_t)NH * SEQ * HD];     // [h][s][d]
__device__ __half hb_v[(size_t)NH * HD * SEQ];     // [h][d][s]  (TRANSPOSED)
__device__ __half hb_att[(size_t)SEQ * DIM];       // [s][h*128+d]
__device__ __half hb_x[(size_t)SEQ * DIM];         // fp16(hidden)
__device__ __half hb_wqt[(size_t)NQKV * DIM];      // fp16(w_qkv^T) [N][K]
__device__ __half hb_wot[(size_t)DIM * DIM];       // fp16(w_out^T) [N][K]

// ---------------- helpers -----------------------------------------------------
__device__ __forceinline__ uint32_t packh2(float a, float b) {
    __half2 h = __floats2half2_rn(a, b);
    return *reinterpret_cast<uint32_t*>(&h);
}

__device__ __forceinline__ void mma16(float* d, const uint32_t* a, const uint32_t* b) {
    asm volatile(
        "mma.sync.aligned.m16n8k16.row.col.f32.f16.f16.f32 "
        "{%0,%1,%2,%3},{%4,%5,%6,%7},{%8,%9},{%0,%1,%2,%3};"
        : "+f"(d[0]), "+f"(d[1]), "+f"(d[2]), "+f"(d[3])
        : "r"(a[0]), "r"(a[1]), "r"(a[2]), "r"(a[3]), "r"(b[0]), "r"(b[1]));
}

__device__ __forceinline__ void cpa16(uint32_t s, const void* g, bool v) {
    asm volatile("cp.async.ca.shared.global [%0], [%1], 16, %2;"
                 :: "r"(s), "l"(g), "r"(v ? 16 : 0));
}
__device__ __forceinline__ void cpcommit() {
    asm volatile("cp.async.commit_group;");
}
template<int N> __device__ __forceinline__ void cpwait() {
    asm volatile("cp.async.wait_group %0;" :: "n"(N));
}

// ---------------- pre-passes --------------------------------------------------
__global__ void __launch_bounds__(256) cvt_h(
    const float* __restrict__ in, __half* __restrict__ out, int n4)
{
    int i = blockIdx.x * 256 + threadIdx.x;
    if (i < n4) {
        float4 v = ((const float4*)in)[i];
        uint2 o;
        o.x = packh2(v.x, v.y);
        o.y = packh2(v.z, v.w);
        ((uint2*)out)[i] = o;
    }
}

__global__ void __launch_bounds__(256) transpose_h(
    const float* __restrict__ in, __half* __restrict__ out, int R, int C)
{
    __shared__ float tb[32][33];
    const int bx = blockIdx.x * 32;
    const int by = blockIdx.y * 32;
    const int tx = threadIdx.x & 31, ty = threadIdx.x >> 5;
#pragma unroll
    for (int i = 0; i < 4; i++)
        tb[ty + i * 8][tx] = in[(size_t)(by + ty + i * 8) * C + bx + tx];
    __syncthreads();
#pragma unroll
    for (int i = 0; i < 4; i++)
        out[(size_t)(bx + ty + i * 8) * R + by + tx] =
            __float2half_rn(tb[tx][ty + i * 8]);
}

__global__ void __launch_bounds__(256) v_transpose()
{
    __shared__ float tb[32][33];
    const int s0 = blockIdx.x * 32;
    const int d0 = blockIdx.y * 32;
    const int tx = threadIdx.x & 31, ty = threadIdx.x >> 5;
#pragma unroll
    for (int i = 0; i < 4; i++) {
        const int s = s0 + ty + i * 8;
        if (s < SEQ)
            tb[ty + i * 8][tx] = buf_qkv[(size_t)s * NQKV + 2 * DIM + d0 + tx];
    }
    __syncthreads();
    if (s0 + tx < SEQ) {
#pragma unroll
        for (int i = 0; i < 4; i++)
            hb_v[(size_t)(d0 + ty + i * 8) * SEQ + s0 + tx] =
                __float2half_rn(tb[tx][ty + i * 8]);
    }
}

// ---------------- fp16 mma.sync GEMM, 3-stage cp.async (R8 structure) ---------
#define GKT 64
#define GTILEB (128*128)                 // 16KB per operand tile
#define GEMM_SMEM (3 * 2 * GTILEB)       // 96KB

__global__ void __launch_bounds__(256, 2) gemm_h(
    int M, int N, int K,
    const __half* __restrict__ A, const __half* __restrict__ BT,
    const float* __restrict__ bias, float* __restrict__ C)
{
    extern __shared__ char smg[];
    const uint32_t sbase = (uint32_t)__cvta_generic_to_shared(smg);
    const int tid = threadIdx.x, wid = tid >> 5, lane = tid & 31;
    const int g = lane >> 2, t = lane & 3;
    const int bm = blockIdx.y * 128, bn = blockIdx.x * 128;
    const int warpm = (wid >> 2) * 64, warpn = (wid & 3) * 32;

    const int lrow = tid >> 1;
    const int lcb = (tid & 1) * 4;
    const bool aval = (bm + lrow) < M;
    const __half* Ag = A + (size_t)(bm + lrow) * K + lcb * 8;
    const __half* Bg = BT + (size_t)(bn + lrow) * K + lcb * 8;
    uint32_t soff[4];
#pragma unroll
    for (int i = 0; i < 4; i++)
        soff[i] = (uint32_t)(lrow * 128 + (((lcb + i) * 16) ^ ((lrow & 7) * 16)));

    auto issue = [&](int st, int kt) {
        const uint32_t ab = sbase + st * 2 * GTILEB;
        const __half* ga = Ag + kt * GKT;
        const __half* gb = Bg + kt * GKT;
#pragma unroll
        for (int i = 0; i < 4; i++) {
            cpa16(ab + soff[i], ga + i * 8, aval);
            cpa16(ab + GTILEB + soff[i], gb + i * 8, true);
        }
    };

    const uint32_t* smw = (const uint32_t*)smg;

    float acc[4][4][4];
#pragma unroll
    for (int i = 0; i < 4; i++)
#pragma unroll
        for (int j = 0; j < 4; j++)
#pragma unroll
            for (int c = 0; c < 4; c++) acc[i][j][c] = 0.f;

    const int NT = K / GKT;
    issue(0, 0); cpcommit();
    issue(1, 1); cpcommit();

    for (int kt = 0; kt < NT; kt++) {
        cpwait<1>();
        __syncthreads();

        const uint32_t tw = (kt % 3) * 2 * (GTILEB / 4);
#pragma unroll
        for (int ks = 0; ks < 4; ks++) {
            uint32_t af[4][4], bf[4][2];
#pragma unroll
            for (int i = 0; i < 4; i++) {
                const int r0 = warpm + i * 16 + g, r1 = r0 + 8;
                const uint32_t x0 = (uint32_t)((ks * 8 + t) ^ ((r0 & 7) * 4));
                const uint32_t x1 = (uint32_t)((ks * 8 + t) ^ ((r1 & 7) * 4));
                const uint32_t y0 = (uint32_t)((ks * 8 + 4 + t) ^ ((r0 & 7) * 4));
                const uint32_t y1 = (uint32_t)((ks * 8 + 4 + t) ^ ((r1 & 7) * 4));
                af[i][0] = smw[tw + r0 * 32 + x0];
                af[i][1] = smw[tw + r1 * 32 + x1];
                af[i][2] = smw[tw + r0 * 32 + y0];
                af[i][3] = smw[tw + r1 * 32 + y1];
            }
#pragma unroll
            for (int j = 0; j < 4; j++) {
                const int rn = warpn + j * 8 + g;
                const uint32_t x = (uint32_t)((ks * 8 + t) ^ ((rn & 7) * 4));
                const uint32_t y = (uint32_t)((ks * 8 + 4 + t) ^ ((rn & 7) * 4));
                bf[j][0] = smw[tw + GTILEB / 4 + rn * 32 + x];
                bf[j][1] = smw[tw + GTILEB / 4 + rn * 32 + y];
            }
#pragma unroll
            for (int i = 0; i < 4; i++)
#pragma unroll
                for (int j = 0; j < 4; j++)
                    mma16(acc[i][j], af[i], bf[j]);
        }
        __syncthreads();
        if (kt + 2 < NT) issue((kt + 2) % 3, kt + 2);
        cpcommit();
    }

    // epilogue with bias
#pragma unroll
    for (int i = 0; i < 4; i++) {
        const int r0 = bm + warpm + i * 16 + g;
#pragma unroll
        for (int j = 0; j < 4; j++) {
            const int c0 = bn + warpn + j * 8 + 2 * t;
            const float b0 = bias[c0], b1 = bias[c0 + 1];
            if (r0 < M) {
                float2 v; v.x = acc[i][j][0] + b0; v.y = acc[i][j][1] + b1;
                *(float2*)(C + (size_t)r0 * N + c0) = v;
            }
            if (r0 + 8 < M) {
                float2 v; v.x = acc[i][j][2] + b0; v.y = acc[i][j][3] + b1;
                *(float2*)(C + (size_t)(r0 + 8) * N + c0) = v;
            }
        }
    }
}

// ---------------- RMSNorm + RoPE (Q,K); outputs fp16 --------------------------
__global__ void __launch_bounds__(256) norm_rope(
    const float* __restrict__ gamma_q, const float* __restrict__ gamma_k,
    const float* __restrict__ cosb, const float* __restrict__ sinb)
{
    const int s = blockIdx.x;
    const int tid = threadIdx.x;
    __shared__ float row[DIM];
    __shared__ float red[8];
    __shared__ float s_scale;

    const float* base = buf_qkv + (size_t)s * NQKV;
    const float qsc = 0.08838834764831845f;

    for (int sel = 0; sel < 2; sel++) {
        const float* src = base + sel * DIM;
        const float* gamma = sel ? gamma_k : gamma_q;
        __half* dst = sel ? hb_k : hb_q;
        const float post = sel ? 1.f : qsc;

        float ss = 0.f;
        for (int j = tid; j < DIM; j += 256) {
            float x = src[j];
            row[j] = x;
            ss += x * x;
        }
#pragma unroll
        for (int off = 16; off > 0; off >>= 1)
            ss += __shfl_xor_sync(0xffffffffu, ss, off);
        if ((tid & 31) == 0) red[tid >> 5] = ss;
        __syncthreads();
        if (tid == 0) {
            float tt = 0.f;
#pragma unroll
            for (int wq = 0; wq < 8; wq++) tt += red[wq];
            s_scale = rsqrtf(tt / (float)DIM + 1e-6f);
        }
        __syncthreads();
        const float scale = s_scale;

        for (int j2 = tid; j2 < DIM / 2; j2 += 256) {
            float x1 = row[2 * j2]     * scale * gamma[2 * j2];
            float x2 = row[2 * j2 + 1] * scale * gamma[2 * j2 + 1];
            const int i = j2 & 63;
            const float cc = cosb[s * 64 + i];
            const float sn = sinb[s * 64 + i];
            const int h = (2 * j2) >> 7;
            const int d = (2 * j2) & 127;
            const uint32_t p = packh2((x1 * cc - x2 * sn) * post,
                                      (x1 * sn + x2 * cc) * post);
            *(uint32_t*)(dst + ((size_t)h * SEQ + s) * HD + d) = p;
        }
        __syncthreads();
    }
}

// ---------------- fp16 flash attention (R12 + LPT block scheduling) -----------
// 1D grid of 588 CTAs: bids 0..299 are the LONG q-tiles (qt 24..48, kmax=3120),
// bids 300..587 the SHORT ones (qt 0..23, kmax=1560). Longest-first scheduling
// minimizes single-wave makespan (entire grid is resident at once).
#define ATT_BQ 64
#define N_QT 49
#define N_LONG 25
#define N_SHORT 24
#define ATT_GRID (N_QT * NH)
#define KSTH 136
#define VSTH 72
#define PSTH 72
#define ATT_SMEM ((64*KSTH + 128*VSTH + 64*PSTH) * 2)

__global__ void __launch_bounds__(128) flash_h()
{
    extern __shared__ char sma[];
    __half* Kb  = (__half*)sma;                        // [64][136]
    __half* VTb = Kb + 64 * KSTH;                      // [128][72]
    uint32_t* Ps32 = (uint32_t*)(VTb + 128 * VSTH);    // [64][36] words
    const uint32_t kbase  = (uint32_t)__cvta_generic_to_shared(Kb);
    const uint32_t vtbase = (uint32_t)__cvta_generic_to_shared(VTb);
    const uint32_t* Kw = (const uint32_t*)Kb;
    const uint32_t* Vw = (const uint32_t*)VTb;

    // LPT decode: long tiles first
    const int bid = blockIdx.x;
    int h, qt;
    if (bid < N_LONG * NH) {
        h = bid / N_LONG;
        qt = N_SHORT + (bid % N_LONG);     // 24..48
    } else {
        const int i2 = bid - N_LONG * NH;
        h = i2 / N_SHORT;
        qt = i2 % N_SHORT;                 // 0..23
    }
    const int q0 = qt * ATT_BQ;

    const int tid = threadIdx.x, w = tid >> 5, lane = tid & 31;
    const int g = lane >> 2, t = lane & 3;

    const uint32_t* Qg = (const uint32_t*)(hb_q + (size_t)h * SEQ * HD);
    const __half* Kg = hb_k + (size_t)h * SEQ * HD;
    const __half* Vt = hb_v + (size_t)h * HD * SEQ;    // [d][s]

    const int r0 = q0 + w * 16 + g, r1 = r0 + 8;
    const int lr0 = w * 16 + g, lr1 = lr0 + 8;

    auto issueK = [&](int k0) {
        const int krow = tid >> 1;                 // 0..63
        const int cb = (tid & 1) * 8;
        const __half* src = Kg + (size_t)(k0 + krow) * HD + cb * 8;
        const uint32_t dst = kbase + (uint32_t)(krow * KSTH * 2 + cb * 16);
        const bool v = (k0 + krow) < SEQ;
#pragma unroll
        for (int c = 0; c < 8; c++)
            cpa16(dst + c * 16, src + c * 8, v);
    };
    auto issueV = [&](int k0) {
        const __half* src = Vt + (size_t)tid * SEQ + k0;   // row d = tid
        const uint32_t dst = vtbase + (uint32_t)(tid * VSTH * 2);
#pragma unroll
        for (int c = 0; c < 8; c++)
            cpa16(dst + c * 16, src + c * 8, (k0 + c * 8) < SEQ);
    };

    // Q a-frags: 8 k16-steps x 4 regs (half2-packed pairs)
    uint32_t qa[8][4];
#pragma unroll
    for (int ks = 0; ks < 8; ks++) {
        qa[ks][0] = (r0 < SEQ) ? Qg[(size_t)r0 * 64 + ks * 8 + t] : 0u;
        qa[ks][1] = (r1 < SEQ) ? Qg[(size_t)r1 * 64 + ks * 8 + t] : 0u;
        qa[ks][2] = (r0 < SEQ) ? Qg[(size_t)r0 * 64 + ks * 8 + 4 + t] : 0u;
        qa[ks][3] = (r1 < SEQ) ? Qg[(size_t)r1 * 64 + ks * 8 + 4 + t] : 0u;
    }

    float O[16][4];
#pragma unroll
    for (int j = 0; j < 16; j++)
#pragma unroll
        for (int c = 0; c < 4; c++) O[j][c] = 0.f;
    float m0 = -1e30f, m1 = -1e30f, l0 = 0.f, l1 = 0.f;

    int rl0 = (r0 / FRAME + 1) * FRAME; if (rl0 > SEQ) rl0 = SEQ;
    int rl1 = (r1 / FRAME + 1) * FRAME; if (rl1 > SEQ) rl1 = SEQ;
    int rlmin = (q0 / FRAME + 1) * FRAME; if (rlmin > SEQ) rlmin = SEQ;
    int qlast = q0 + ATT_BQ - 1; if (qlast > SEQ - 1) qlast = SEQ - 1;
    int kmax = (qlast / FRAME + 1) * FRAME; if (kmax > SEQ) kmax = SEQ;

    issueK(0); cpcommit();
    issueV(0); cpcommit();

    for (int k0 = 0; k0 < kmax; k0 += 64) {
        cpwait<1>();          // K ready
        __syncthreads();

        // S = Q K^T
        float sf[8][4];
#pragma unroll
        for (int j = 0; j < 8; j++)
#pragma unroll
            for (int c = 0; c < 4; c++) sf[j][c] = 0.f;

#pragma unroll
        for (int ks = 0; ks < 8; ks++) {
#pragma unroll
            for (int j = 0; j < 8; j++) {
                const int rn = j * 8 + g;
                uint32_t bf[2];
                bf[0] = Kw[rn * 68 + ks * 8 + t];
                bf[1] = Kw[rn * 68 + ks * 8 + 4 + t];
                mma16(sf[j], qa[ks], bf);
            }
        }

        // mask only when this k-tile straddles a frame boundary
        if (k0 + 64 > rlmin) {
#pragma unroll
            for (int j = 0; j < 8; j++) {
                const int c = k0 + j * 8 + 2 * t;
                sf[j][0] = (c     < rl0) ? sf[j][0] : -1e30f;
                sf[j][1] = (c + 1 < rl0) ? sf[j][1] : -1e30f;
                sf[j][2] = (c     < rl1) ? sf[j][2] : -1e30f;
                sf[j][3] = (c + 1 < rl1) ? sf[j][3] : -1e30f;
            }
        }

        // online softmax
        float mt0 = -1e30f, mt1 = -1e30f;
#pragma unroll
        for (int j = 0; j < 8; j++) {
            mt0 = fmaxf(mt0, fmaxf(sf[j][0], sf[j][1]));
            mt1 = fmaxf(mt1, fmaxf(sf[j][2], sf[j][3]));
        }
        mt0 = fmaxf(mt0, __shfl_xor_sync(0xffffffffu, mt0, 1));
        mt0 = fmaxf(mt0, __shfl_xor_sync(0xffffffffu, mt0, 2));
        mt1 = fmaxf(mt1, __shfl_xor_sync(0xffffffffu, mt1, 1));
        mt1 = fmaxf(mt1, __shfl_xor_sync(0xffffffffu, mt1, 2));

        const float mn0 = fmaxf(m0, mt0), mn1 = fmaxf(m1, mt1);
        const float a0 = __expf(m0 - mn0), a1 = __expf(m1 - mn1);
        float s0 = 0.f, sm1 = 0.f;
#pragma unroll
        for (int j = 0; j < 8; j++) {
            float p0 = __expf(sf[j][0] - mn0);
            float p1 = __expf(sf[j][1] - mn0);
            float p2 = __expf(sf[j][2] - mn1);
            float p3 = __expf(sf[j][3] - mn1);
            s0 += p0 + p1; sm1 += p2 + p3;
            Ps32[lr0 * 36 + j * 4 + t] = packh2(p0, p1);
            Ps32[lr1 * 36 + j * 4 + t] = packh2(p2, p3);
        }
        s0  += __shfl_xor_sync(0xffffffffu, s0, 1);
        s0  += __shfl_xor_sync(0xffffffffu, s0, 2);
        sm1 += __shfl_xor_sync(0xffffffffu, sm1, 1);
        sm1 += __shfl_xor_sync(0xffffffffu, sm1, 2);
        l0 = l0 * a0 + s0;  m0 = mn0;
        l1 = l1 * a1 + sm1; m1 = mn1;
#pragma unroll
        for (int j = 0; j < 16; j++) {
            O[j][0] *= a0; O[j][1] *= a0;
            O[j][2] *= a1; O[j][3] *= a1;
        }

        cpwait<0>();          // V ready
        __syncthreads();      // also publishes Ps

        if (k0 + 64 < kmax) issueK(k0 + 64);
        cpcommit();

        // O += P @ V
#pragma unroll
        for (int ks = 0; ks < 4; ks++) {
            uint32_t af[4];
            af[0] = Ps32[lr0 * 36 + ks * 8 + t];
            af[1] = Ps32[lr1 * 36 + ks * 8 + t];
            af[2] = Ps32[lr0 * 36 + ks * 8 + 4 + t];
            af[3] = Ps32[lr1 * 36 + ks * 8 + 4 + t];
#pragma unroll
            for (int j = 0; j < 16; j++) {
                const int rn = j * 8 + g;
                uint32_t bf[2];
                bf[0] = Vw[rn * 36 + ks * 8 + t];
                bf[1] = Vw[rn * 36 + ks * 8 + 4 + t];
                mma16(O[j], af, bf);
            }
        }
        __syncthreads();      // done with VTb / Ps

        if (k0 + 64 < kmax) issueV(k0 + 64);
        cpcommit();
    }

    // epilogue -> fp16 buf_att (half2 stores)
    const float inv0 = 1.f / l0, inv1 = 1.f / l1;
#pragma unroll
    for (int j = 0; j < 16; j++) {
        const int c = h * HD + j * 8 + 2 * t;
        if (r0 < SEQ)
            *(uint32_t*)(hb_att + (size_t)r0 * DIM + c) =
                packh2(O[j][0] * inv0, O[j][1] * inv0);
        if (r1 < SEQ)
            *(uint32_t*)(hb_att + (size_t)r1 * DIM + c) =
                packh2(O[j][2] * inv1, O[j][3] * inv1);
    }
}

// ---------------- launch ------------------------------------------------------
extern "C" void kernel_launch(void* const* d_in, const int* in_sizes, int n_in,
                              void* d_out, int out_size)
{
    const float* hidden  = (const float*)d_in[0];
    const float* cosb    = (const float*)d_in[1];
    const float* sinb    = (const float*)d_in[2];
    const float* w_qkv   = (const float*)d_in[3];
    const float* b_qkv   = (const float*)d_in[4];
    const float* gamma_q = (const float*)d_in[5];
    const float* gamma_k = (const float*)d_in[6];
    const float* w_out   = (const float*)d_in[7];
    const float* b_out   = (const float*)d_in[8];
    float* out = (float*)d_out;

    float* qkv_p;
    __half *x_p, *wqt_p, *wot_p, *att_p;
    cudaGetSymbolAddress((void**)&qkv_p, buf_qkv);
    cudaGetSymbolAddress((void**)&x_p,   hb_x);
    cudaGetSymbolAddress((void**)&wqt_p, hb_wqt);
    cudaGetSymbolAddress((void**)&wot_p, hb_wot);
    cudaGetSymbolAddress((void**)&att_p, hb_att);

    cudaFuncSetAttribute(gemm_h, cudaFuncAttributeMaxDynamicSharedMemorySize,
                         GEMM_SMEM);
    cudaFuncSetAttribute(flash_h, cudaFuncAttributeMaxDynamicSharedMemorySize,
                         ATT_SMEM);

    // 0) pre-passes: fp16 conversion + weight transposes
    int n4 = SEQ * DIM / 4;
    cvt_h<<<(n4 + 255) / 256, 256>>>(hidden, x_p, n4);
    {
        dim3 gt(NQKV / 32, DIM / 32);
        transpose_h<<<gt, 256>>>(w_qkv, wqt_p, DIM, NQKV);
        dim3 go(DIM / 32, DIM / 32);
        transpose_h<<<go, 256>>>(w_out, wot_p, DIM, DIM);
    }

    // 1) QKV projection (fp16 tensor cores, fp32 out)
    dim3 g1(NQKV / 128, (SEQ + 127) / 128);
    gemm_h<<<g1, 256, GEMM_SMEM>>>(SEQ, NQKV, DIM, x_p, wqt_p, b_qkv, qkv_p);

    // 2) RMSNorm + RoPE (Q,K fp16) and V transpose (fp16)
    norm_rope<<<SEQ, 256>>>(gamma_q, gamma_k, cosb, sinb);
    {
        dim3 gv((SEQ + 31) / 32, DIM / 32);
        v_transpose<<<gv, 256>>>();
    }

    // 3) attention (1D grid, long tiles first)
    flash_h<<<ATT_GRID, 128, ATT_SMEM>>>();

    // 4) output projection
    dim3 g4(DIM / 128, (SEQ + 127) / 128);
    gemm_h<<<g4, 256, GEMM_SMEM>>>(SEQ, DIM, DIM, att_p, wot_p, b_out, out);
}

// round 14
// speedup vs baseline: 1.7598x; 1.1139x over previous
#include <cuda_runtime.h>
#include <cuda_fp16.h>
#include <cstdint>

#define SEQ 3120
#define DIM 1536
#define NH 12
#define HD 128
#define FRAME 1560
#define NQKV (3*DIM)

// ---------------- scratch (device globals; no allocation allowed) -------------
__device__ float  buf_qkv[(size_t)SEQ * NQKV];     // fp32 QKV proj output
__device__ __half hb_q[(size_t)NH * SEQ * HD];     // [h][s][d], pre-scaled
__device__ __half hb_k[(size_t)NH * SEQ * HD];     // [h][s][d]
__device__ __half hb_v[(size_t)NH * HD * SEQ];     // [h][d][s]  (TRANSPOSED)
__device__ __half hb_att[(size_t)SEQ * DIM];       // [s][h*128+d]
__device__ __half hb_x[(size_t)SEQ * DIM];         // fp16(hidden)
__device__ __half hb_wqt[(size_t)NQKV * DIM];      // fp16(w_qkv^T) [N][K]
__device__ __half hb_wot[(size_t)DIM * DIM];       // fp16(w_out^T) [N][K]

// ---------------- helpers -----------------------------------------------------
__device__ __forceinline__ uint32_t packh2(float a, float b) {
    __half2 h = __floats2half2_rn(a, b);
    return *reinterpret_cast<uint32_t*>(&h);
}

__device__ __forceinline__ void mma16(float* d, const uint32_t* a, const uint32_t* b) {
    asm volatile(
        "mma.sync.aligned.m16n8k16.row.col.f32.f16.f16.f32 "
        "{%0,%1,%2,%3},{%4,%5,%6,%7},{%8,%9},{%0,%1,%2,%3};"
        : "+f"(d[0]), "+f"(d[1]), "+f"(d[2]), "+f"(d[3])
        : "r"(a[0]), "r"(a[1]), "r"(a[2]), "r"(a[3]), "r"(b[0]), "r"(b[1]));
}

__device__ __forceinline__ void cpa16(uint32_t s, const void* g, bool v) {
    asm volatile("cp.async.ca.shared.global [%0], [%1], 16, %2;"
                 :: "r"(s), "l"(g), "r"(v ? 16 : 0));
}
__device__ __forceinline__ void cpcommit() {
    asm volatile("cp.async.commit_group;");
}
template<int N> __device__ __forceinline__ void cpwait() {
    asm volatile("cp.async.wait_group %0;" :: "n"(N));
}

// ---------------- pre-passes --------------------------------------------------
__global__ void __launch_bounds__(256) cvt_h(
    const float* __restrict__ in, __half* __restrict__ out, int n4)
{
    int i = blockIdx.x * 256 + threadIdx.x;
    if (i < n4) {
        float4 v = ((const float4*)in)[i];
        uint2 o;
        o.x = packh2(v.x, v.y);
        o.y = packh2(v.z, v.w);
        ((uint2*)out)[i] = o;
    }
}

__global__ void __launch_bounds__(256) transpose_h(
    const float* __restrict__ in, __half* __restrict__ out, int R, int C)
{
    __shared__ float tb[32][33];
    const int bx = blockIdx.x * 32;
    const int by = blockIdx.y * 32;
    const int tx = threadIdx.x & 31, ty = threadIdx.x >> 5;
#pragma unroll
    for (int i = 0; i < 4; i++)
        tb[ty + i * 8][tx] = in[(size_t)(by + ty + i * 8) * C + bx + tx];
    __syncthreads();
#pragma unroll
    for (int i = 0; i < 4; i++)
        out[(size_t)(bx + ty + i * 8) * R + by + tx] =
            __float2half_rn(tb[tx][ty + i * 8]);
}

__global__ void __launch_bounds__(256) v_transpose()
{
    __shared__ float tb[32][33];
    const int s0 = blockIdx.x * 32;
    const int d0 = blockIdx.y * 32;
    const int tx = threadIdx.x & 31, ty = threadIdx.x >> 5;
#pragma unroll
    for (int i = 0; i < 4; i++) {
        const int s = s0 + ty + i * 8;
        if (s < SEQ)
            tb[ty + i * 8][tx] = buf_qkv[(size_t)s * NQKV + 2 * DIM + d0 + tx];
    }
    __syncthreads();
    if (s0 + tx < SEQ) {
#pragma unroll
        for (int i = 0; i < 4; i++)
            hb_v[(size_t)(d0 + ty + i * 8) * SEQ + s0 + tx] =
                __float2half_rn(tb[tx][ty + i * 8]);
    }
}

// ---------------- fp16 mma.sync GEMM, 3-stage cp.async (R8 structure) ---------
#define GKT 64
#define GTILEB (128*128)                 // 16KB per operand tile
#define GEMM_SMEM (3 * 2 * GTILEB)       // 96KB

__global__ void __launch_bounds__(256, 2) gemm_h(
    int M, int N, int K,
    const __half* __restrict__ A, const __half* __restrict__ BT,
    const float* __restrict__ bias, float* __restrict__ C)
{
    extern __shared__ char smg[];
    const uint32_t sbase = (uint32_t)__cvta_generic_to_shared(smg);
    const int tid = threadIdx.x, wid = tid >> 5, lane = tid & 31;
    const int g = lane >> 2, t = lane & 3;
    const int bm = blockIdx.y * 128, bn = blockIdx.x * 128;
    const int warpm = (wid >> 2) * 64, warpn = (wid & 3) * 32;

    const int lrow = tid >> 1;
    const int lcb = (tid & 1) * 4;
    const bool aval = (bm + lrow) < M;
    const __half* Ag = A + (size_t)(bm + lrow) * K + lcb * 8;
    const __half* Bg = BT + (size_t)(bn + lrow) * K + lcb * 8;
    uint32_t soff[4];
#pragma unroll
    for (int i = 0; i < 4; i++)
        soff[i] = (uint32_t)(lrow * 128 + (((lcb + i) * 16) ^ ((lrow & 7) * 16)));

    auto issue = [&](int st, int kt) {
        const uint32_t ab = sbase + st * 2 * GTILEB;
        const __half* ga = Ag + kt * GKT;
        const __half* gb = Bg + kt * GKT;
#pragma unroll
        for (int i = 0; i < 4; i++) {
            cpa16(ab + soff[i], ga + i * 8, aval);
            cpa16(ab + GTILEB + soff[i], gb + i * 8, true);
        }
    };

    const uint32_t* smw = (const uint32_t*)smg;

    float acc[4][4][4];
#pragma unroll
    for (int i = 0; i < 4; i++)
#pragma unroll
        for (int j = 0; j < 4; j++)
#pragma unroll
            for (int c = 0; c < 4; c++) acc[i][j][c] = 0.f;

    const int NT = K / GKT;
    issue(0, 0); cpcommit();
    issue(1, 1); cpcommit();

    for (int kt = 0; kt < NT; kt++) {
        cpwait<1>();
        __syncthreads();

        const uint32_t tw = (kt % 3) * 2 * (GTILEB / 4);
#pragma unroll
        for (int ks = 0; ks < 4; ks++) {
            uint32_t af[4][4], bf[4][2];
#pragma unroll
            for (int i = 0; i < 4; i++) {
                const int r0 = warpm + i * 16 + g, r1 = r0 + 8;
                const uint32_t x0 = (uint32_t)((ks * 8 + t) ^ ((r0 & 7) * 4));
                const uint32_t x1 = (uint32_t)((ks * 8 + t) ^ ((r1 & 7) * 4));
                const uint32_t y0 = (uint32_t)((ks * 8 + 4 + t) ^ ((r0 & 7) * 4));
                const uint32_t y1 = (uint32_t)((ks * 8 + 4 + t) ^ ((r1 & 7) * 4));
                af[i][0] = smw[tw + r0 * 32 + x0];
                af[i][1] = smw[tw + r1 * 32 + x1];
                af[i][2] = smw[tw + r0 * 32 + y0];
                af[i][3] = smw[tw + r1 * 32 + y1];
            }
#pragma unroll
            for (int j = 0; j < 4; j++) {
                const int rn = warpn + j * 8 + g;
                const uint32_t x = (uint32_t)((ks * 8 + t) ^ ((rn & 7) * 4));
                const uint32_t y = (uint32_t)((ks * 8 + 4 + t) ^ ((rn & 7) * 4));
                bf[j][0] = smw[tw + GTILEB / 4 + rn * 32 + x];
                bf[j][1] = smw[tw + GTILEB / 4 + rn * 32 + y];
            }
#pragma unroll
            for (int i = 0; i < 4; i++)
#pragma unroll
                for (int j = 0; j < 4; j++)
                    mma16(acc[i][j], af[i], bf[j]);
        }
        __syncthreads();
        if (kt + 2 < NT) issue((kt + 2) % 3, kt + 2);
        cpcommit();
    }

    // epilogue with bias
#pragma unroll
    for (int i = 0; i < 4; i++) {
        const int r0 = bm + warpm + i * 16 + g;
#pragma unroll
        for (int j = 0; j < 4; j++) {
            const int c0 = bn + warpn + j * 8 + 2 * t;
            const float b0 = bias[c0], b1 = bias[c0 + 1];
            if (r0 < M) {
                float2 v; v.x = acc[i][j][0] + b0; v.y = acc[i][j][1] + b1;
                *(float2*)(C + (size_t)r0 * N + c0) = v;
            }
            if (r0 + 8 < M) {
                float2 v; v.x = acc[i][j][2] + b0; v.y = acc[i][j][3] + b1;
                *(float2*)(C + (size_t)(r0 + 8) * N + c0) = v;
            }
        }
    }
}

// ---------------- RMSNorm + RoPE (Q,K); outputs fp16 --------------------------
__global__ void __launch_bounds__(256) norm_rope(
    const float* __restrict__ gamma_q, const float* __restrict__ gamma_k,
    const float* __restrict__ cosb, const float* __restrict__ sinb)
{
    const int s = blockIdx.x;
    const int tid = threadIdx.x;
    __shared__ float row[DIM];
    __shared__ float red[8];
    __shared__ float s_scale;

    const float* base = buf_qkv + (size_t)s * NQKV;
    const float qsc = 0.08838834764831845f;

    for (int sel = 0; sel < 2; sel++) {
        const float* src = base + sel * DIM;
        const float* gamma = sel ? gamma_k : gamma_q;
        __half* dst = sel ? hb_k : hb_q;
        const float post = sel ? 1.f : qsc;

        float ss = 0.f;
        for (int j = tid; j < DIM; j += 256) {
            float x = src[j];
            row[j] = x;
            ss += x * x;
        }
#pragma unroll
        for (int off = 16; off > 0; off >>= 1)
            ss += __shfl_xor_sync(0xffffffffu, ss, off);
        if ((tid & 31) == 0) red[tid >> 5] = ss;
        __syncthreads();
        if (tid == 0) {
            float tt = 0.f;
#pragma unroll
            for (int wq = 0; wq < 8; wq++) tt += red[wq];
            s_scale = rsqrtf(tt / (float)DIM + 1e-6f);
        }
        __syncthreads();
        const float scale = s_scale;

        for (int j2 = tid; j2 < DIM / 2; j2 += 256) {
            float x1 = row[2 * j2]     * scale * gamma[2 * j2];
            float x2 = row[2 * j2 + 1] * scale * gamma[2 * j2 + 1];
            const int i = j2 & 63;
            const float cc = cosb[s * 64 + i];
            const float sn = sinb[s * 64 + i];
            const int h = (2 * j2) >> 7;
            const int d = (2 * j2) & 127;
            const uint32_t p = packh2((x1 * cc - x2 * sn) * post,
                                      (x1 * sn + x2 * cc) * post);
            *(uint32_t*)(dst + ((size_t)h * SEQ + s) * HD + d) = p;
        }
        __syncthreads();
    }
}

// ---------------- fp16 flash attention (R13 + P-in-registers) -----------------
// 1D grid, LPT order: bids 0..299 long q-tiles (kmax=3120), 300..587 short.
// P never touches smem: the S-output frag layout IS the PV A-frag layout
// (tile j -> k-chunk j>>1, half j&1), so exp'd probs pack straight into regs.
#define ATT_BQ 64
#define N_QT 49
#define N_LONG 25
#define N_SHORT 24
#define ATT_GRID (N_QT * NH)
#define KSTH 136
#define VSTH 72
#define ATT_SMEM ((64*KSTH + 128*VSTH) * 2)

__global__ void __launch_bounds__(128) flash_h()
{
    extern __shared__ char sma[];
    __half* Kb  = (__half*)sma;                        // [64][136]
    __half* VTb = Kb + 64 * KSTH;                      // [128][72]
    const uint32_t kbase  = (uint32_t)__cvta_generic_to_shared(Kb);
    const uint32_t vtbase = (uint32_t)__cvta_generic_to_shared(VTb);
    const uint32_t* Kw = (const uint32_t*)Kb;
    const uint32_t* Vw = (const uint32_t*)VTb;

    // LPT decode: long tiles first
    const int bid = blockIdx.x;
    int h, qt;
    if (bid < N_LONG * NH) {
        h = bid / N_LONG;
        qt = N_SHORT + (bid % N_LONG);     // 24..48
    } else {
        const int i2 = bid - N_LONG * NH;
        h = i2 / N_SHORT;
        qt = i2 % N_SHORT;                 // 0..23
    }
    const int q0 = qt * ATT_BQ;

    const int tid = threadIdx.x, w = tid >> 5, lane = tid & 31;
    const int g = lane >> 2, t = lane & 3;

    const uint32_t* Qg = (const uint32_t*)(hb_q + (size_t)h * SEQ * HD);
    const __half* Kg = hb_k + (size_t)h * SEQ * HD;
    const __half* Vt = hb_v + (size_t)h * HD * SEQ;    // [d][s]

    const int r0 = q0 + w * 16 + g, r1 = r0 + 8;

    auto issueK = [&](int k0) {
        const int krow = tid >> 1;                 // 0..63
        const int cb = (tid & 1) * 8;
        const __half* src = Kg + (size_t)(k0 + krow) * HD + cb * 8;
        const uint32_t dst = kbase + (uint32_t)(krow * KSTH * 2 + cb * 16);
        const bool v = (k0 + krow) < SEQ;
#pragma unroll
        for (int c = 0; c < 8; c++)
            cpa16(dst + c * 16, src + c * 8, v);
    };
    auto issueV = [&](int k0) {
        const __half* src = Vt + (size_t)tid * SEQ + k0;   // row d = tid
        const uint32_t dst = vtbase + (uint32_t)(tid * VSTH * 2);
#pragma unroll
        for (int c = 0; c < 8; c++)
            cpa16(dst + c * 16, src + c * 8, (k0 + c * 8) < SEQ);
    };

    // Q a-frags: 8 k16-steps x 4 regs (half2-packed pairs)
    uint32_t qa[8][4];
#pragma unroll
    for (int ks = 0; ks < 8; ks++) {
        qa[ks][0] = (r0 < SEQ) ? Qg[(size_t)r0 * 64 + ks * 8 + t] : 0u;
        qa[ks][1] = (r1 < SEQ) ? Qg[(size_t)r1 * 64 + ks * 8 + t] : 0u;
        qa[ks][2] = (r0 < SEQ) ? Qg[(size_t)r0 * 64 + ks * 8 + 4 + t] : 0u;
        qa[ks][3] = (r1 < SEQ) ? Qg[(size_t)r1 * 64 + ks * 8 + 4 + t] : 0u;
    }

    float O[16][4];
#pragma unroll
    for (int j = 0; j < 16; j++)
#pragma unroll
        for (int c = 0; c < 4; c++) O[j][c] = 0.f;
    float m0 = -1e30f, m1 = -1e30f, l0 = 0.f, l1 = 0.f;

    int rl0 = (r0 / FRAME + 1) * FRAME; if (rl0 > SEQ) rl0 = SEQ;
    int rl1 = (r1 / FRAME + 1) * FRAME; if (rl1 > SEQ) rl1 = SEQ;
    int rlmin = (q0 / FRAME + 1) * FRAME; if (rlmin > SEQ) rlmin = SEQ;
    int qlast = q0 + ATT_BQ - 1; if (qlast > SEQ - 1) qlast = SEQ - 1;
    int kmax = (qlast / FRAME + 1) * FRAME; if (kmax > SEQ) kmax = SEQ;

    issueK(0); cpcommit();
    issueV(0); cpcommit();

    for (int k0 = 0; k0 < kmax; k0 += 64) {
        cpwait<1>();          // K ready
        __syncthreads();

        // S = Q K^T
        float sf[8][4];
#pragma unroll
        for (int j = 0; j < 8; j++)
#pragma unroll
            for (int c = 0; c < 4; c++) sf[j][c] = 0.f;

#pragma unroll
        for (int ks = 0; ks < 8; ks++) {
#pragma unroll
            for (int j = 0; j < 8; j++) {
                const int rn = j * 8 + g;
                uint32_t bf[2];
                bf[0] = Kw[rn * 68 + ks * 8 + t];
                bf[1] = Kw[rn * 68 + ks * 8 + 4 + t];
                mma16(sf[j], qa[ks], bf);
            }
        }

        // mask only when this k-tile straddles a frame boundary
        if (k0 + 64 > rlmin) {
#pragma unroll
            for (int j = 0; j < 8; j++) {
                const int c = k0 + j * 8 + 2 * t;
                sf[j][0] = (c     < rl0) ? sf[j][0] : -1e30f;
                sf[j][1] = (c + 1 < rl0) ? sf[j][1] : -1e30f;
                sf[j][2] = (c     < rl1) ? sf[j][2] : -1e30f;
                sf[j][3] = (c + 1 < rl1) ? sf[j][3] : -1e30f;
            }
        }

        // online softmax -> P packed directly into A-frag registers
        float mt0 = -1e30f, mt1 = -1e30f;
#pragma unroll
        for (int j = 0; j < 8; j++) {
            mt0 = fmaxf(mt0, fmaxf(sf[j][0], sf[j][1]));
            mt1 = fmaxf(mt1, fmaxf(sf[j][2], sf[j][3]));
        }
        mt0 = fmaxf(mt0, __shfl_xor_sync(0xffffffffu, mt0, 1));
        mt0 = fmaxf(mt0, __shfl_xor_sync(0xffffffffu, mt0, 2));
        mt1 = fmaxf(mt1, __shfl_xor_sync(0xffffffffu, mt1, 1));
        mt1 = fmaxf(mt1, __shfl_xor_sync(0xffffffffu, mt1, 2));

        const float mn0 = fmaxf(m0, mt0), mn1 = fmaxf(m1, mt1);
        const float a0 = __expf(m0 - mn0), a1 = __expf(m1 - mn1);
        float s0 = 0.f, sm1 = 0.f;
        uint32_t pa[4][4];    // PV a-frags: [k-chunk][{gLo,g8Lo,gHi,g8Hi}]
#pragma unroll
        for (int j = 0; j < 8; j++) {
            float p0 = __expf(sf[j][0] - mn0);
            float p1 = __expf(sf[j][1] - mn0);
            float p2 = __expf(sf[j][2] - mn1);
            float p3 = __expf(sf[j][3] - mn1);
            s0 += p0 + p1; sm1 += p2 + p3;
            pa[j >> 1][(j & 1) * 2 + 0] = packh2(p0, p1);
            pa[j >> 1][(j & 1) * 2 + 1] = packh2(p2, p3);
        }
        s0  += __shfl_xor_sync(0xffffffffu, s0, 1);
        s0  += __shfl_xor_sync(0xffffffffu, s0, 2);
        sm1 += __shfl_xor_sync(0xffffffffu, sm1, 1);
        sm1 += __shfl_xor_sync(0xffffffffu, sm1, 2);
        l0 = l0 * a0 + s0;  m0 = mn0;
        l1 = l1 * a1 + sm1; m1 = mn1;
#pragma unroll
        for (int j = 0; j < 16; j++) {
            O[j][0] *= a0; O[j][1] *= a0;
            O[j][2] *= a1; O[j][3] *= a1;
        }

        cpwait<0>();          // V ready
        __syncthreads();      // all warps done reading Kb -> safe to refill

        if (k0 + 64 < kmax) issueK(k0 + 64);
        cpcommit();

        // O += P @ V (P from registers)
#pragma unroll
        for (int ks = 0; ks < 4; ks++) {
#pragma unroll
            for (int j = 0; j < 16; j++) {
                const int rn = j * 8 + g;
                uint32_t bf[2];
                bf[0] = Vw[rn * 36 + ks * 8 + t];
                bf[1] = Vw[rn * 36 + ks * 8 + 4 + t];
                mma16(O[j], pa[ks], bf);
            }
        }
        __syncthreads();      // done with VTb

        if (k0 + 64 < kmax) issueV(k0 + 64);
        cpcommit();
    }

    // epilogue -> fp16 buf_att (half2 stores)
    const float inv0 = 1.f / l0, inv1 = 1.f / l1;
#pragma unroll
    for (int j = 0; j < 16; j++) {
        const int c = h * HD + j * 8 + 2 * t;
        if (r0 < SEQ)
            *(uint32_t*)(hb_att + (size_t)r0 * DIM + c) =
                packh2(O[j][0] * inv0, O[j][1] * inv0);
        if (r1 < SEQ)
            *(uint32_t*)(hb_att + (size_t)r1 * DIM + c) =
                packh2(O[j][2] * inv1, O[j][3] * inv1);
    }
}

// ---------------- launch ------------------------------------------------------
extern "C" void kernel_launch(void* const* d_in, const int* in_sizes, int n_in,
                              void* d_out, int out_size)
{
    const float* hidden  = (const float*)d_in[0];
    const float* cosb    = (const float*)d_in[1];
    const float* sinb    = (const float*)d_in[2];
    const float* w_qkv   = (const float*)d_in[3];
    const float* b_qkv   = (const float*)d_in[4];
    const float* gamma_q = (const float*)d_in[5];
    const float* gamma_k = (const float*)d_in[6];
    const float* w_out   = (const float*)d_in[7];
    const float* b_out   = (const float*)d_in[8];
    float* out = (float*)d_out;

    float* qkv_p;
    __half *x_p, *wqt_p, *wot_p, *att_p;
    cudaGetSymbolAddress((void**)&qkv_p, buf_qkv);
    cudaGetSymbolAddress((void**)&x_p,   hb_x);
    cudaGetSymbolAddress((void**)&wqt_p, hb_wqt);
    cudaGetSymbolAddress((void**)&wot_p, hb_wot);
    cudaGetSymbolAddress((void**)&att_p, hb_att);

    cudaFuncSetAttribute(gemm_h, cudaFuncAttributeMaxDynamicSharedMemorySize,
                         GEMM_SMEM);
    cudaFuncSetAttribute(flash_h, cudaFuncAttributeMaxDynamicSharedMemorySize,
                         ATT_SMEM);

    // 0) pre-passes: fp16 conversion + weight transposes
    int n4 = SEQ * DIM / 4;
    cvt_h<<<(n4 + 255) / 256, 256>>>(hidden, x_p, n4);
    {
        dim3 gt(NQKV / 32, DIM / 32);
        transpose_h<<<gt, 256>>>(w_qkv, wqt_p, DIM, NQKV);
        dim3 go(DIM / 32, DIM / 32);
        transpose_h<<<go, 256>>>(w_out, wot_p, DIM, DIM);
    }

    // 1) QKV projection (fp16 tensor cores, fp32 out)
    dim3 g1(NQKV / 128, (SEQ + 127) / 128);
    gemm_h<<<g1, 256, GEMM_SMEM>>>(SEQ, NQKV, DIM, x_p, wqt_p, b_qkv, qkv_p);

    // 2) RMSNorm + RoPE (Q,K fp16) and V transpose (fp16)
    norm_rope<<<SEQ, 256>>>(gamma_q, gamma_k, cosb, sinb);
    {
        dim3 gv((SEQ + 31) / 32, DIM / 32);
        v_transpose<<<gv, 256>>>();
    }

    // 3) attention (1D grid, long tiles first)
    flash_h<<<ATT_GRID, 128, ATT_SMEM>>>();

    // 4) output projection
    dim3 g4(DIM / 128, (SEQ + 127) / 128);
    gemm_h<<<g4, 256, GEMM_SMEM>>>(SEQ, DIM, DIM, att_p, wot_p, b_out, out);
}